// round 4
// baseline (speedup 1.0000x reference)
#include <cuda_runtime.h>
#include <cuda_bf16.h>
#include <math.h>
#include <stdint.h>

// Problem constants
#define LNUM 8
#define DDIM 1024
#define HNUM 16
#define DKDIM 64
#define FDIM 4096
#define VDIM 32000
#define SDIM 1024
#define BNUM 2
#define MROWS (BNUM * SDIM)   // 2048

// ---------------- scratch (device globals; no runtime allocation) ----------
__device__ float g_x[MROWS * DDIM];
__device__ float g_q[MROWS * DDIM];
__device__ float g_k[MROWS * DDIM];
__device__ float g_v[MROWS * DDIM];
// bf16 hi/lo activation buffers
__device__ __nv_bfloat16 g_hh  [MROWS * DDIM];
__device__ __nv_bfloat16 g_hl  [MROWS * DDIM];
__device__ __nv_bfloat16 g_atth[MROWS * DDIM];
__device__ __nv_bfloat16 g_attl[MROWS * DDIM];
__device__ __nv_bfloat16 g_midh[MROWS * FDIM];
__device__ __nv_bfloat16 g_midl[MROWS * FDIM];
// bf16 hi/lo weight buffers (converted once per launch)
__device__ __nv_bfloat16 g_wqh[LNUM * DDIM * DDIM];
__device__ __nv_bfloat16 g_wql[LNUM * DDIM * DDIM];
__device__ __nv_bfloat16 g_wkh[LNUM * DDIM * DDIM];
__device__ __nv_bfloat16 g_wkl[LNUM * DDIM * DDIM];
__device__ __nv_bfloat16 g_wvh[LNUM * DDIM * DDIM];
__device__ __nv_bfloat16 g_wvl[LNUM * DDIM * DDIM];
__device__ __nv_bfloat16 g_woh[LNUM * DDIM * DDIM];
__device__ __nv_bfloat16 g_wol[LNUM * DDIM * DDIM];
__device__ __nv_bfloat16 g_w1h[LNUM * DDIM * FDIM];
__device__ __nv_bfloat16 g_w1l[LNUM * DDIM * FDIM];
__device__ __nv_bfloat16 g_w2h[LNUM * DDIM * FDIM];
__device__ __nv_bfloat16 g_w2l[LNUM * DDIM * FDIM];
__device__ __nv_bfloat16 g_wouth[DDIM * VDIM];
__device__ __nv_bfloat16 g_woutl[DDIM * VDIM];

// ======================= PTX helpers (portable, sm_80+) =====================
__device__ __forceinline__ uint32_t smem_u32(const void* p) {
    uint32_t a;
    asm("{ .reg .u64 t; cvta.to.shared.u64 t, %1; cvt.u32.u64 %0, t; }"
        : "=r"(a) : "l"(p));
    return a;
}
__device__ __forceinline__ void ldsm4(uint32_t* r, uint32_t addr) {
    asm volatile("ldmatrix.sync.aligned.m8n8.x4.shared.b16 {%0,%1,%2,%3}, [%4];"
        : "=r"(r[0]), "=r"(r[1]), "=r"(r[2]), "=r"(r[3]) : "r"(addr));
}
__device__ __forceinline__ void ldsm4t(uint32_t* r, uint32_t addr) {
    asm volatile("ldmatrix.sync.aligned.m8n8.x4.trans.shared.b16 {%0,%1,%2,%3}, [%4];"
        : "=r"(r[0]), "=r"(r[1]), "=r"(r[2]), "=r"(r[3]) : "r"(addr));
}
__device__ __forceinline__ void mma16816(float* c, const uint32_t* a,
                                         const uint32_t* b) {
    asm volatile(
        "mma.sync.aligned.m16n8k16.row.col.f32.bf16.bf16.f32 "
        "{%0,%1,%2,%3}, {%4,%5,%6,%7}, {%8,%9}, {%0,%1,%2,%3};"
        : "+f"(c[0]), "+f"(c[1]), "+f"(c[2]), "+f"(c[3])
        : "r"(a[0]), "r"(a[1]), "r"(a[2]), "r"(a[3]), "r"(b[0]), "r"(b[1]));
}
__device__ __forceinline__ void cpa16(uint32_t d, const void* s) {
    asm volatile("cp.async.cg.shared.global [%0], [%1], 16;" :: "r"(d), "l"(s));
}
#define CP_COMMIT() asm volatile("cp.async.commit_group;" ::: "memory")
#define CP_WAIT1()  asm volatile("cp.async.wait_group 1;" ::: "memory")

__device__ __forceinline__ uint32_t packbf2(__nv_bfloat16 a, __nv_bfloat16 b) {
    __nv_bfloat162 t;
    t.x = a; t.y = b;
    return *reinterpret_cast<uint32_t*>(&t);
}
__device__ __forceinline__ void cvt_split4(float4 v, uint32_t& h01, uint32_t& h23,
                                           uint32_t& l01, uint32_t& l23) {
    __nv_bfloat16 hx = __float2bfloat16(v.x);
    __nv_bfloat16 hy = __float2bfloat16(v.y);
    __nv_bfloat16 hz = __float2bfloat16(v.z);
    __nv_bfloat16 hw = __float2bfloat16(v.w);
    float rx = v.x - __bfloat162float(hx);
    float ry = v.y - __bfloat162float(hy);
    float rz = v.z - __bfloat162float(hz);
    float rw = v.w - __bfloat162float(hw);
    h01 = packbf2(hx, hy);
    h23 = packbf2(hz, hw);
    l01 = packbf2(__float2bfloat16(rx), __float2bfloat16(ry));
    l23 = packbf2(__float2bfloat16(rz), __float2bfloat16(rw));
}

// ---------------- split kernel: fp32 -> bf16 hi + bf16 lo -------------------
__global__ void split_kernel(const float4* __restrict__ src,
                             uint2* __restrict__ hi, uint2* __restrict__ lo,
                             int n4)
{
    int i = blockIdx.x * blockDim.x + threadIdx.x;
    int stride = gridDim.x * blockDim.x;
    for (; i < n4; i += stride) {
        float4 v = src[i];
        uint32_t h01, h23, l01, l23;
        cvt_split4(v, h01, h23, l01, l23);
        hi[i] = make_uint2(h01, h23);
        lo[i] = make_uint2(l01, l23);
    }
}

// ---------------- async-pipelined tensor-core GEMM --------------------------
// C[M,N] = (Ah+Al)[M,K] @ (Bh+Bl)[K,N] + bias  (hh + hl + lh terms)
// CTA 128x128x32, 8 warps (2x4), warp tile 64x32, 3-stage cp.async ring.
#define BM 128
#define BN 128
#define BK 32
// smem elem strides (bf16): A row 40 (80B), B row 136 (272B)
#define A_STG 10240            // bytes per A stage (128*80)
#define B_STG 8704             // bytes per B stage (32*272)
#define AHI_B 0
#define ALO_B (3 * A_STG)      // 30720
#define BHI_B (2 * ALO_B)      // 61440
#define BLO_B (BHI_B + 3 * B_STG) // 87552
#define SMEM_MM (BLO_B + 3 * B_STG) // 113664 bytes

template<bool RELU, bool RES, bool OBF>
__global__ void __launch_bounds__(256, 1)
gemm_as(const __nv_bfloat16* __restrict__ Ah, const __nv_bfloat16* __restrict__ Al,
        const __nv_bfloat16* __restrict__ Bh, const __nv_bfloat16* __restrict__ Bl,
        const float* __restrict__ bias, float* __restrict__ C,
        __nv_bfloat16* __restrict__ Ch, __nv_bfloat16* __restrict__ Cl,
        int M, int N, int K)
{
    extern __shared__ char smem[];
    uint32_t sb = smem_u32(smem);

    int tid  = threadIdx.x;
    int wid  = tid >> 5;
    int lane = tid & 31;
    int bn = blockIdx.x * BN;
    int bm = blockIdx.y * BM;
    int wm = (wid >> 2) * 64;
    int wn = (wid & 3) * 32;

    // cp.async source pointers (per thread)
    const __nv_bfloat16* aH = Ah + (size_t)(bm + (tid >> 1)) * K + (tid & 1) * 16;
    const __nv_bfloat16* aL = Al + (size_t)(bm + (tid >> 1)) * K + (tid & 1) * 16;
    const __nv_bfloat16* bH = Bh + (size_t)(tid >> 3) * N + bn + (tid & 7) * 16;
    const __nv_bfloat16* bL = Bl + (size_t)(tid >> 3) * N + bn + (tid & 7) * 16;
    // cp.async smem dst bases (stage 0)
    uint32_t adst = sb + (uint32_t)((tid >> 1) * 80 + (tid & 1) * 32);
    uint32_t bdst = sb + BHI_B + (uint32_t)((tid >> 3) * 272 + (tid & 7) * 32);

#define LOADS(s)                                                              \
    {                                                                         \
        int buf_ = (s) % 3;                                                   \
        uint32_t ad = adst + buf_ * A_STG;                                    \
        const __nv_bfloat16* a1 = aH + (s) * BK;                              \
        const __nv_bfloat16* a2 = aL + (s) * BK;                              \
        cpa16(ad, a1); cpa16(ad + 16, a1 + 8);                                \
        cpa16(ad + ALO_B, a2); cpa16(ad + ALO_B + 16, a2 + 8);                \
        uint32_t bd = bdst + buf_ * B_STG;                                    \
        const __nv_bfloat16* b1 = bH + (size_t)(s) * BK * N;                  \
        const __nv_bfloat16* b2 = bL + (size_t)(s) * BK * N;                  \
        cpa16(bd, b1); cpa16(bd + 16, b1 + 8);                                \
        cpa16(bd + (BLO_B - BHI_B), b2);                                      \
        cpa16(bd + (BLO_B - BHI_B) + 16, b2 + 8);                             \
    }

    float acc[4][4][4];
    #pragma unroll
    for (int i = 0; i < 4; i++)
        #pragma unroll
        for (int j = 0; j < 4; j++)
            #pragma unroll
            for (int r = 0; r < 4; r++) acc[i][j][r] = 0.f;

    const int nst = K / BK;
    LOADS(0); CP_COMMIT();
    LOADS(1); CP_COMMIT();

    for (int s = 0; s < nst; s++) {
        CP_WAIT1();
        __syncthreads();
        if (s + 2 < nst) LOADS(s + 2);
        CP_COMMIT();

        int buf = s % 3;
        uint32_t abase = sb + AHI_B + buf * A_STG;
        uint32_t bbase = sb + BHI_B + buf * B_STG;

        #pragma unroll
        for (int kk = 0; kk < 2; kk++) {
            uint32_t ah[4][4], al[4][4], bh[2][4], bl[2][4];
            int arow = wm + (lane & 15);
            int kcol = kk * 16 + (lane >> 4) * 8;
            #pragma unroll
            for (int mt = 0; mt < 4; mt++) {
                uint32_t eo = (uint32_t)((arow + mt * 16) * 40 + kcol) * 2;
                ldsm4(ah[mt], abase + eo);
                ldsm4(al[mt], abase + ALO_B + eo);
            }
            int krow = kk * 16 + (lane & 15);
            int ncol = wn + (lane >> 4) * 8;
            #pragma unroll
            for (int nt2 = 0; nt2 < 2; nt2++) {
                uint32_t eo = (uint32_t)(krow * 136 + ncol + nt2 * 16) * 2;
                ldsm4t(bh[nt2], bbase + eo);
                ldsm4t(bl[nt2], bbase + (BLO_B - BHI_B) + eo);
            }
            #pragma unroll
            for (int mt = 0; mt < 4; mt++)
                #pragma unroll
                for (int nt = 0; nt < 4; nt++) {
                    const uint32_t* bhp = &bh[nt >> 1][(nt & 1) * 2];
                    const uint32_t* blp = &bl[nt >> 1][(nt & 1) * 2];
                    mma16816(acc[mt][nt], ah[mt], bhp);
                    mma16816(acc[mt][nt], ah[mt], blp);
                    mma16816(acc[mt][nt], al[mt], bhp);
                }
        }
    }

    // ---- epilogue ----
    #pragma unroll
    for (int mt = 0; mt < 4; mt++) {
        int grow = bm + wm + mt * 16 + (lane >> 2);
        #pragma unroll
        for (int nt = 0; nt < 4; nt++) {
            int gcol = bn + wn + nt * 8 + (lane & 3) * 2;
            float2 bb = *(const float2*)(bias + gcol);
            float v0 = acc[mt][nt][0] + bb.x;
            float v1 = acc[mt][nt][1] + bb.y;
            float v2 = acc[mt][nt][2] + bb.x;
            float v3 = acc[mt][nt][3] + bb.y;
            if (RELU) {
                v0 = fmaxf(v0, 0.f); v1 = fmaxf(v1, 0.f);
                v2 = fmaxf(v2, 0.f); v3 = fmaxf(v3, 0.f);
            }
            if (OBF) {
                size_t o0 = (size_t)grow * N + gcol;
                size_t o1 = (size_t)(grow + 8) * N + gcol;
                __nv_bfloat16 h0 = __float2bfloat16(v0);
                __nv_bfloat16 h1 = __float2bfloat16(v1);
                __nv_bfloat16 h2 = __float2bfloat16(v2);
                __nv_bfloat16 h3 = __float2bfloat16(v3);
                *(uint32_t*)(Ch + o0) = packbf2(h0, h1);
                *(uint32_t*)(Ch + o1) = packbf2(h2, h3);
                *(uint32_t*)(Cl + o0) = packbf2(
                    __float2bfloat16(v0 - __bfloat162float(h0)),
                    __float2bfloat16(v1 - __bfloat162float(h1)));
                *(uint32_t*)(Cl + o1) = packbf2(
                    __float2bfloat16(v2 - __bfloat162float(h2)),
                    __float2bfloat16(v3 - __bfloat162float(h3)));
            } else {
                float* c0 = C + (size_t)grow * N;
                float* c1 = C + (size_t)(grow + 8) * N;
                if (RES) {
                    float2 o0 = *(const float2*)(c0 + gcol);
                    float2 o1 = *(const float2*)(c1 + gcol);
                    v0 += o0.x; v1 += o0.y; v2 += o1.x; v3 += o1.y;
                }
                *(float2*)(c0 + gcol) = make_float2(v0, v1);
                *(float2*)(c1 + gcol) = make_float2(v2, v3);
            }
        }
    }
#undef LOADS
}

// ---------------- embedding -------------------------------------------------
__global__ void embed_kernel(const int* __restrict__ ids,
                             const float* __restrict__ tok,
                             const float* __restrict__ pos,
                             float* __restrict__ x)
{
    int row = blockIdx.x;
    int s   = row % SDIM;
    int id  = ids[row];
    int tid = threadIdx.x;
    const float* tr = tok + (size_t)id * DDIM;
    const float* pr = pos + (size_t)s  * DDIM;
    float* xr = x + (size_t)row * DDIM;
    #pragma unroll
    for (int i = 0; i < 4; i++) {
        int c = tid + i * 256;
        xr[c] = tr[c] + pr[c];
    }
}

// ---------------- layernorm (bf16 hi/lo output) ------------------------------
__global__ void ln_kernel(const float* __restrict__ x,
                          const float* __restrict__ g,
                          const float* __restrict__ b,
                          __nv_bfloat16* __restrict__ oh,
                          __nv_bfloat16* __restrict__ ol)
{
    __shared__ float red[256];
    int row = blockIdx.x;
    int tid = threadIdx.x;
    const float* xr = x + (size_t)row * DDIM;

    float vals[4];
    float s = 0.f;
    #pragma unroll
    for (int i = 0; i < 4; i++) { vals[i] = xr[tid + i * 256]; s += vals[i]; }
    red[tid] = s; __syncthreads();
    for (int o = 128; o > 0; o >>= 1) {
        if (tid < o) red[tid] += red[tid + o];
        __syncthreads();
    }
    float mean = red[0] * (1.0f / DDIM);
    __syncthreads();

    float vs = 0.f;
    #pragma unroll
    for (int i = 0; i < 4; i++) { float d = vals[i] - mean; vs += d * d; }
    red[tid] = vs; __syncthreads();
    for (int o = 128; o > 0; o >>= 1) {
        if (tid < o) red[tid] += red[tid + o];
        __syncthreads();
    }
    float inv = rsqrtf(red[0] * (1.0f / DDIM) + 1e-5f);

    size_t base = (size_t)row * DDIM;
    #pragma unroll
    for (int i = 0; i < 4; i++) {
        int c = tid + i * 256;
        float val = (vals[i] - mean) * inv * g[c] + b[c];
        __nv_bfloat16 h = __float2bfloat16(val);
        oh[base + c] = h;
        ol[base + c] = __float2bfloat16(val - __bfloat162float(h));
    }
}

// ---------------- causal attention (flash-style, 64x64 tiles) ---------------
#define ATT_SMEM_FLOATS (5 * 64 * 65 + 3 * 64)

__global__ void attn_kernel(const float* __restrict__ q,
                            const float* __restrict__ k,
                            const float* __restrict__ v,
                            __nv_bfloat16* __restrict__ oh,
                            __nv_bfloat16* __restrict__ ol)
{
    extern __shared__ float sm[];
    float* Qs  = sm;
    float* Ks  = Qs + 64 * 65;
    float* Vs  = Ks + 64 * 65;
    float* Ss  = Vs + 64 * 65;
    float* Os  = Ss + 64 * 65;
    float* mrow = Os + 64 * 65;
    float* lrow = mrow + 64;
    float* arow = lrow + 64;

    int qt = blockIdx.x, hh = blockIdx.y, bb = blockIdx.z;
    int tid = threadIdx.x;
    const float scale = 0.125f;

    int r  = tid >> 2;
    int c0 = (tid & 3) * 16;
    int tx = tid & 15;
    int ty = tid >> 4;

    size_t qbase = ((size_t)(bb * SDIM) + qt * 64) * DDIM + hh * DKDIM;

    #pragma unroll
    for (int i = 0; i < 16; i++) {
        int c = c0 + i;
        Qs[r * 65 + c] = q[qbase + (size_t)r * DDIM + c];
        Os[r * 65 + c] = 0.f;
    }
    if (tid < 64) { mrow[tid] = -1e30f; lrow[tid] = 0.f; }
    __syncthreads();

    for (int kt = 0; kt <= qt; kt++) {
        size_t kbase = ((size_t)(bb * SDIM) + kt * 64) * DDIM + hh * DKDIM;
        #pragma unroll
        for (int i = 0; i < 16; i++) {
            int c = c0 + i;
            Ks[r * 65 + c] = k[kbase + (size_t)r * DDIM + c];
            Vs[r * 65 + c] = v[kbase + (size_t)r * DDIM + c];
        }
        __syncthreads();

        {
            float a4[4][4];
            #pragma unroll
            for (int i = 0; i < 4; i++)
                #pragma unroll
                for (int j = 0; j < 4; j++) a4[i][j] = 0.f;
            for (int d = 0; d < 64; d++) {
                float qa[4], kb[4];
                #pragma unroll
                for (int i = 0; i < 4; i++) qa[i] = Qs[(ty * 4 + i) * 65 + d];
                #pragma unroll
                for (int j = 0; j < 4; j++) kb[j] = Ks[(tx * 4 + j) * 65 + d];
                #pragma unroll
                for (int i = 0; i < 4; i++)
                    #pragma unroll
                    for (int j = 0; j < 4; j++) a4[i][j] += qa[i] * kb[j];
            }
            #pragma unroll
            for (int i = 0; i < 4; i++) {
                int rr = ty * 4 + i;
                #pragma unroll
                for (int j = 0; j < 4; j++) {
                    int cc = tx * 4 + j;
                    float val = a4[i][j] * scale;
                    if (kt == qt && cc > rr) val = -1e30f;
                    Ss[rr * 65 + cc] = val;
                }
            }
        }
        __syncthreads();

        if (tid < 64) {
            int rr = tid;
            float tm = -1e30f;
            for (int c = 0; c < 64; c++) tm = fmaxf(tm, Ss[rr * 65 + c]);
            float mold = mrow[rr];
            float mnew = fmaxf(mold, tm);
            float al = expf(mold - mnew);
            float sum = 0.f;
            for (int c = 0; c < 64; c++) {
                float p = expf(Ss[rr * 65 + c] - mnew);
                Ss[rr * 65 + c] = p;
                sum += p;
            }
            lrow[rr] = lrow[rr] * al + sum;
            mrow[rr] = mnew;
            arow[rr] = al;
        }
        __syncthreads();

        {
            float oacc[4][4];
            #pragma unroll
            for (int i = 0; i < 4; i++) {
                float al = arow[ty * 4 + i];
                #pragma unroll
                for (int j = 0; j < 4; j++)
                    oacc[i][j] = Os[(ty * 4 + i) * 65 + tx * 4 + j] * al;
            }
            for (int jj = 0; jj < 64; jj++) {
                float pa[4], vb[4];
                #pragma unroll
                for (int i = 0; i < 4; i++) pa[i] = Ss[(ty * 4 + i) * 65 + jj];
                #pragma unroll
                for (int j = 0; j < 4; j++) vb[j] = Vs[jj * 65 + tx * 4 + j];
                #pragma unroll
                for (int i = 0; i < 4; i++)
                    #pragma unroll
                    for (int j = 0; j < 4; j++) oacc[i][j] += pa[i] * vb[j];
            }
            #pragma unroll
            for (int i = 0; i < 4; i++)
                #pragma unroll
                for (int j = 0; j < 4; j++)
                    Os[(ty * 4 + i) * 65 + tx * 4 + j] = oacc[i][j];
        }
        __syncthreads();
    }

    float invl = 1.f / lrow[r];
    #pragma unroll
    for (int i = 0; i < 16; i++) {
        int c = c0 + i;
        float val = Os[r * 65 + c] * invl;
        __nv_bfloat16 h = __float2bfloat16(val);
        size_t idx = qbase + (size_t)r * DDIM + c;
        oh[idx] = h;
        ol[idx] = __float2bfloat16(val - __bfloat162float(h));
    }
}

// ---------------- host orchestration ----------------------------------------
extern "C" void kernel_launch(void* const* d_in, const int* in_sizes, int n_in,
                              void* d_out, int out_size)
{
    const int*   ids   = (const int*)  d_in[0];
    const float* tok   = (const float*)d_in[1];
    const float* pos   = (const float*)d_in[2];
    const float* Wq    = (const float*)d_in[3];
    const float* bq    = (const float*)d_in[4];
    const float* Wk    = (const float*)d_in[5];
    const float* bk    = (const float*)d_in[6];
    const float* Wv    = (const float*)d_in[7];
    const float* bv    = (const float*)d_in[8];
    const float* Wo    = (const float*)d_in[9];
    const float* bo    = (const float*)d_in[10];
    const float* W1    = (const float*)d_in[11];
    const float* b1    = (const float*)d_in[12];
    const float* W2    = (const float*)d_in[13];
    const float* b2    = (const float*)d_in[14];
    const float* ln1g  = (const float*)d_in[15];
    const float* ln1b  = (const float*)d_in[16];
    const float* ln2g  = (const float*)d_in[17];
    const float* ln2b  = (const float*)d_in[18];
    const float* lnfg  = (const float*)d_in[19];
    const float* lnfb  = (const float*)d_in[20];
    const float* Wout  = (const float*)d_in[21];
    const float* bout  = (const float*)d_in[22];
    float* out = (float*)d_out;

    float *x, *q, *k, *v;
    __nv_bfloat16 *hh, *hl, *atth, *attl, *midh, *midl;
    __nv_bfloat16 *wqh, *wql, *wkh, *wkl, *wvh, *wvl, *woh, *wol;
    __nv_bfloat16 *w1h, *w1l, *w2h, *w2l, *wouth, *woutl;
    cudaGetSymbolAddress((void**)&x, g_x);
    cudaGetSymbolAddress((void**)&q, g_q);
    cudaGetSymbolAddress((void**)&k, g_k);
    cudaGetSymbolAddress((void**)&v, g_v);
    cudaGetSymbolAddress((void**)&hh, g_hh);
    cudaGetSymbolAddress((void**)&hl, g_hl);
    cudaGetSymbolAddress((void**)&atth, g_atth);
    cudaGetSymbolAddress((void**)&attl, g_attl);
    cudaGetSymbolAddress((void**)&midh, g_midh);
    cudaGetSymbolAddress((void**)&midl, g_midl);
    cudaGetSymbolAddress((void**)&wqh, g_wqh);
    cudaGetSymbolAddress((void**)&wql, g_wql);
    cudaGetSymbolAddress((void**)&wkh, g_wkh);
    cudaGetSymbolAddress((void**)&wkl, g_wkl);
    cudaGetSymbolAddress((void**)&wvh, g_wvh);
    cudaGetSymbolAddress((void**)&wvl, g_wvl);
    cudaGetSymbolAddress((void**)&woh, g_woh);
    cudaGetSymbolAddress((void**)&wol, g_wol);
    cudaGetSymbolAddress((void**)&w1h, g_w1h);
    cudaGetSymbolAddress((void**)&w1l, g_w1l);
    cudaGetSymbolAddress((void**)&w2h, g_w2h);
    cudaGetSymbolAddress((void**)&w2l, g_w2l);
    cudaGetSymbolAddress((void**)&wouth, g_wouth);
    cudaGetSymbolAddress((void**)&woutl, g_woutl);

    const int attSmem = ATT_SMEM_FLOATS * (int)sizeof(float);
    cudaFuncSetAttribute(attn_kernel, cudaFuncAttributeMaxDynamicSharedMemorySize, attSmem);
    cudaFuncSetAttribute(gemm_as<false, false, false>, cudaFuncAttributeMaxDynamicSharedMemorySize, SMEM_MM);
    cudaFuncSetAttribute(gemm_as<false, true,  false>, cudaFuncAttributeMaxDynamicSharedMemorySize, SMEM_MM);
    cudaFuncSetAttribute(gemm_as<true,  false, true >, cudaFuncAttributeMaxDynamicSharedMemorySize, SMEM_MM);

    // one-shot weight conversion (fp32 -> bf16 hi/lo)
    const int nDD4 = LNUM * DDIM * DDIM / 4;
    const int nDF4 = LNUM * DDIM * FDIM / 4;
    const int nV4  = DDIM * VDIM / 4;
    split_kernel<<<4096, 256>>>((const float4*)Wq,   (uint2*)wqh,   (uint2*)wql,   nDD4);
    split_kernel<<<4096, 256>>>((const float4*)Wk,   (uint2*)wkh,   (uint2*)wkl,   nDD4);
    split_kernel<<<4096, 256>>>((const float4*)Wv,   (uint2*)wvh,   (uint2*)wvl,   nDD4);
    split_kernel<<<4096, 256>>>((const float4*)Wo,   (uint2*)woh,   (uint2*)wol,   nDD4);
    split_kernel<<<4096, 256>>>((const float4*)W1,   (uint2*)w1h,   (uint2*)w1l,   nDF4);
    split_kernel<<<4096, 256>>>((const float4*)W2,   (uint2*)w2h,   (uint2*)w2l,   nDF4);
    split_kernel<<<4096, 256>>>((const float4*)Wout, (uint2*)wouth, (uint2*)woutl, nV4);

    embed_kernel<<<MROWS, 256>>>(ids, tok, pos, x);

    dim3 gD (DDIM / BN, MROWS / BM);   // 8  x 16
    dim3 gF (FDIM / BN, MROWS / BM);   // 32 x 16
    dim3 gV (VDIM / BN, MROWS / BM);   // 250 x 16
    dim3 gAtt(SDIM / 64, HNUM, BNUM);

    for (int l = 0; l < LNUM; l++) {
        size_t oDD = (size_t)l * DDIM * DDIM;
        size_t oDF = (size_t)l * DDIM * FDIM;

        ln_kernel<<<MROWS, 256>>>(x, ln1g + l * DDIM, ln1b + l * DDIM, hh, hl);

        gemm_as<false, false, false><<<gD, 256, SMEM_MM>>>(
            hh, hl, wqh + oDD, wql + oDD, bq + l * DDIM, q, nullptr, nullptr,
            MROWS, DDIM, DDIM);
        gemm_as<false, false, false><<<gD, 256, SMEM_MM>>>(
            hh, hl, wkh + oDD, wkl + oDD, bk + l * DDIM, k, nullptr, nullptr,
            MROWS, DDIM, DDIM);
        gemm_as<false, false, false><<<gD, 256, SMEM_MM>>>(
            hh, hl, wvh + oDD, wvl + oDD, bv + l * DDIM, v, nullptr, nullptr,
            MROWS, DDIM, DDIM);

        attn_kernel<<<gAtt, 256, attSmem>>>(q, k, v, atth, attl);

        gemm_as<false, true, false><<<gD, 256, SMEM_MM>>>(
            atth, attl, woh + oDD, wol + oDD, bo + l * DDIM, x, nullptr, nullptr,
            MROWS, DDIM, DDIM);

        ln_kernel<<<MROWS, 256>>>(x, ln2g + l * DDIM, ln2b + l * DDIM, hh, hl);

        gemm_as<true, false, true><<<gF, 256, SMEM_MM>>>(
            hh, hl, w1h + oDF, w1l + oDF, b1 + l * FDIM, nullptr, midh, midl,
            MROWS, FDIM, DDIM);
        gemm_as<false, true, false><<<gD, 256, SMEM_MM>>>(
            midh, midl, w2h + oDF, w2l + oDF, b2 + l * DDIM, x, nullptr, nullptr,
            MROWS, DDIM, FDIM);
    }

    ln_kernel<<<MROWS, 256>>>(x, lnfg, lnfb, hh, hl);
    gemm_as<false, false, false><<<gV, 256, SMEM_MM>>>(
        hh, hl, wouth, woutl, bout, out, nullptr, nullptr,
        MROWS, VDIM, DDIM);
}